// round 13
// baseline (speedup 1.0000x reference)
#include <cuda_runtime.h>
#include <cuda_bf16.h>

#define N_NODES  100000
#define N_EDGES  3200000
#define N_GRAPHS 512
#define HID      16
#define LABELS   10
#define VOCAB    128

#define SCAN_BLK 1024
#define SCAN_NB  ((N_NODES + SCAN_BLK - 1) / SCAN_BLK)   // 98

// ---------------- scratch (device globals; no allocation allowed) ----------
__device__ int    g_deg   [N_NODES];
__device__ int    g_off   [N_NODES];
__device__ int    g_cursor[N_NODES];
__device__ int    g_bsum  [SCAN_NB];
__device__ int    g_bbase [SCAN_NB];
__device__ int    g_csr   [N_EDGES];
__device__ float  g_dinv  [N_NODES];
__device__ float4 g_a1    [N_NODES * 4];    // EW[x[i]] * dinv[i]
__device__ float4 g_a2    [N_NODES * 4];    // (h1 @ W2) * dinv[i]
__device__ float4 g_EW    [VOCAB * 4];      // emb @ W1
__device__ float  g_sums  [N_GRAPHS * HID];
__device__ float  g_cnt   [N_GRAPHS];

__device__ __forceinline__ void red4(float4* p, float a, float b, float c, float d) {
    asm volatile("red.global.add.v4.f32 [%0], {%1,%2,%3,%4};"
                 :: "l"(p), "f"(a), "f"(b), "f"(c), "f"(d) : "memory");
}
__device__ __forceinline__ void redf(float* p, float v) {
    asm volatile("red.global.add.f32 [%0], %1;" :: "l"(p), "f"(v) : "memory");
}
__device__ __forceinline__ void redu(int* p) {
    asm volatile("red.global.add.u32 [%0], %1;" :: "l"(p), "r"(1u) : "memory");
}

// ---------------- build (R3-proven chain) -----------------------------------

__global__ __launch_bounds__(256) void k_init() {
    int i = blockIdx.x * blockDim.x + threadIdx.x;
    if (i < N_NODES) g_deg[i] = 0;
    if (i < N_GRAPHS * HID) g_sums[i] = 0.0f;
    if (i < N_GRAPHS) g_cnt[i] = 0.0f;
}

__global__ __launch_bounds__(256) void k_deg(const int* __restrict__ dst, int E) {
    int e = blockIdx.x * blockDim.x + threadIdx.x;
    if (e < E) redu(&g_deg[dst[e]]);
}

// shfl-based block scan (1024/block)
__global__ __launch_bounds__(SCAN_BLK) void k_scan1() {
    __shared__ int wtot[32];
    int gid = blockIdx.x * SCAN_BLK + threadIdx.x;
    int lane = threadIdx.x & 31, wid = threadIdx.x >> 5;
    int v = (gid < N_NODES) ? g_deg[gid] : 0;
    int x = v;
#pragma unroll
    for (int o = 1; o < 32; o <<= 1) {
        int t = __shfl_up_sync(0xffffffffu, x, o);
        if (lane >= o) x += t;
    }
    if (lane == 31) wtot[wid] = x;
    __syncthreads();
    if (threadIdx.x < 32) {
        int w = wtot[threadIdx.x];
        int y = w;
#pragma unroll
        for (int o = 1; o < 32; o <<= 1) {
            int t = __shfl_up_sync(0xffffffffu, y, o);
            if (threadIdx.x >= o) y += t;
        }
        wtot[threadIdx.x] = y - w;
        if (threadIdx.x == 31) g_bsum[blockIdx.x] = y;
    }
    __syncthreads();
    if (gid < N_NODES) g_off[gid] = x - v + wtot[wid];
}

// block 0: scan block totals; block 1: EW = emb @ W1
__global__ __launch_bounds__(128) void k_scan2_ew(const float* __restrict__ emb,
                                                  const float* __restrict__ W1) {
    int t = threadIdx.x;
    if (blockIdx.x == 0) {
        __shared__ int s[128];
        int v = (t < SCAN_NB) ? g_bsum[t] : 0;
        s[t] = v;
        __syncthreads();
#pragma unroll
        for (int off = 1; off < 128; off <<= 1) {
            int u = (t >= off) ? s[t - off] : 0;
            __syncthreads();
            s[t] += u;
            __syncthreads();
        }
        if (t < SCAN_NB) g_bbase[t] = s[t] - v;
    } else {
        __shared__ float sW[HID * HID];
        sW[t] = W1[t];
        sW[t + 128] = W1[t + 128];
        __syncthreads();
        float h[HID];
#pragma unroll
        for (int k = 0; k < HID; k++) h[k] = emb[t * HID + k];
#pragma unroll
        for (int q = 0; q < 4; q++) {
            float o[4];
#pragma unroll
            for (int jj = 0; jj < 4; jj++) {
                float s = 0.0f;
#pragma unroll
                for (int k = 0; k < HID; k++) s = fmaf(h[k], sW[k * HID + 4 * q + jj], s);
                o[jj] = s;
            }
            g_EW[t * 4 + q] = make_float4(o[0], o[1], o[2], o[3]);
        }
    }
}

// finalize offsets/cursors/dinv AND emit a1 = EW[x]*dinv
__global__ __launch_bounds__(256) void k_scan3_a1(const int* __restrict__ x) {
    int i = blockIdx.x * blockDim.x + threadIdx.x;
    if (i >= N_NODES) return;
    int o = g_off[i] + g_bbase[i >> 10];
    g_off[i] = o;
    g_cursor[i] = o;
    float di = rsqrtf((float)g_deg[i] + 1.0f);   // +1 self loop
    g_dinv[i] = di;
    const float4* r = &g_EW[x[i] * 4];
#pragma unroll
    for (int q = 0; q < 4; q++) {
        float4 v = r[q];
        g_a1[i * 4 + q] = make_float4(v.x * di, v.y * di, v.z * di, v.w * di);
    }
}

__global__ __launch_bounds__(256) void k_scatter(const int* __restrict__ src,
                                                 const int* __restrict__ dst, int E) {
    int e = blockIdx.x * blockDim.x + threadIdx.x;
    if (e >= E) return;
    int pos = atomicAdd(&g_cursor[dst[e]], 1);
    g_csr[pos] = src[e];
}

// ---------------- gather core (warp/node, 4 lanes per edge) -----------------
__device__ __forceinline__ float4 gather_acc(const float4* __restrict__ val,
                                             int node, int lane) {
    int eq = lane >> 2, fj = lane & 3;
    int off = __ldg(&g_off[node]);
    int deg = __ldg(&g_deg[node]);
    float4 acc = make_float4(0.f, 0.f, 0.f, 0.f);
    for (int base = 0; base < deg; base += 8) {
        int e = base + eq;
        if (e < deg) {
            int s = __ldg(&g_csr[off + e]);
            float4 v = __ldg(&val[s * 4 + fj]);
            acc.x += v.x; acc.y += v.y; acc.z += v.z; acc.w += v.w;
        }
    }
#pragma unroll
    for (int o = 16; o >= 4; o >>= 1) {
        acc.x += __shfl_down_sync(0xffffffffu, acc.x, o);
        acc.y += __shfl_down_sync(0xffffffffu, acc.y, o);
        acc.z += __shfl_down_sync(0xffffffffu, acc.z, o);
        acc.w += __shfl_down_sync(0xffffffffu, acc.w, o);
    }
    return acc;
}

// layer-1 gather + relu + (h1@W2)*dinv -> g_a2   (h1 never hits memory)
__global__ __launch_bounds__(256) void k_gather1_l2(const float* __restrict__ b1,
                                                    const float* __restrict__ W2) {
    __shared__ float sW[HID * HID];
    if (threadIdx.x < HID * HID) sW[threadIdx.x] = W2[threadIdx.x];
    __syncthreads();
    int n = (blockIdx.x * blockDim.x + threadIdx.x) >> 5;
    if (n >= N_NODES) return;
    int lane = threadIdx.x & 31;
    float4 acc = gather_acc(g_a1, n, lane);
    if (lane < 4) {
        float di = __ldg(&g_dinv[n]);
        float4 self = __ldg(&g_a1[n * 4 + lane]);
        float4 b = __ldg((const float4*)b1 + lane);
        float4 h;
        h.x = fmaxf((acc.x + self.x) * di + b.x, 0.0f);
        h.y = fmaxf((acc.y + self.y) * di + b.y, 0.0f);
        h.z = fmaxf((acc.z + self.z) * di + b.z, 0.0f);
        h.w = fmaxf((acc.w + self.w) * di + b.w, 0.0f);
        // o[jb..jb+3] = sum_k h_full[k] * W2[k][jb..jb+3]; h_full spread on lanes 0-3
        int jb = lane * 4;
        float ox = 0.f, oy = 0.f, oz = 0.f, ow = 0.f;
#pragma unroll
        for (int m = 0; m < 4; m++) {
            float4 hm;
            hm.x = __shfl_sync(0x0000000fu, h.x, m);
            hm.y = __shfl_sync(0x0000000fu, h.y, m);
            hm.z = __shfl_sync(0x0000000fu, h.z, m);
            hm.w = __shfl_sync(0x0000000fu, h.w, m);
            const float* w0 = &sW[(4 * m + 0) * HID + jb];
            const float* w1 = &sW[(4 * m + 1) * HID + jb];
            const float* w2 = &sW[(4 * m + 2) * HID + jb];
            const float* w3 = &sW[(4 * m + 3) * HID + jb];
            ox = fmaf(hm.x, w0[0], ox); oy = fmaf(hm.x, w0[1], oy);
            oz = fmaf(hm.x, w0[2], oz); ow = fmaf(hm.x, w0[3], ow);
            ox = fmaf(hm.y, w1[0], ox); oy = fmaf(hm.y, w1[1], oy);
            oz = fmaf(hm.y, w1[2], oz); ow = fmaf(hm.y, w1[3], ow);
            ox = fmaf(hm.z, w2[0], ox); oy = fmaf(hm.z, w2[1], oy);
            oz = fmaf(hm.z, w2[2], oz); ow = fmaf(hm.z, w2[3], ow);
            ox = fmaf(hm.w, w3[0], ox); oy = fmaf(hm.w, w3[1], oy);
            oz = fmaf(hm.w, w3[2], oz); ow = fmaf(hm.w, w3[3], ow);
        }
        g_a2[n * 4 + lane] = make_float4(ox * di, oy * di, oz * di, ow * di);
    }
}

// layer-2 gather + relu + mean-pool reds (no block sync, warps independent;
// h2 never hits memory)
__global__ __launch_bounds__(256) void k_gather2_pool(const float* __restrict__ b2,
                                                      const int* __restrict__ batch) {
    int n = (blockIdx.x * blockDim.x + threadIdx.x) >> 5;
    if (n >= N_NODES) return;
    int lane = threadIdx.x & 31;
    float4 acc = gather_acc(g_a2, n, lane);
    if (lane < 4) {
        float di = __ldg(&g_dinv[n]);
        float4 self = __ldg(&g_a2[n * 4 + lane]);
        float4 b = __ldg((const float4*)b2 + lane);
        float4 o;
        o.x = fmaxf((acc.x + self.x) * di + b.x, 0.0f);
        o.y = fmaxf((acc.y + self.y) * di + b.y, 0.0f);
        o.z = fmaxf((acc.z + self.z) * di + b.z, 0.0f);
        o.w = fmaxf((acc.w + self.w) * di + b.w, 0.0f);
        int bg = __ldg(&batch[n]);            // same addr on 4 lanes: 1 wavefront
        red4((float4*)&g_sums[bg * HID] + lane, o.x, o.y, o.z, o.w);
        if (lane == 0) redf(&g_cnt[bg], 1.0f);
    }
}

__global__ __launch_bounds__(256) void k_final(const float* __restrict__ Wc,
                                               const float* __restrict__ bc,
                                               float* __restrict__ out) {
    int g = blockIdx.x * blockDim.x + threadIdx.x;
    if (g >= N_GRAPHS) return;
    float inv = 1.0f / fmaxf(g_cnt[g], 1.0f);
    float p[HID];
#pragma unroll
    for (int k = 0; k < HID; k++) p[k] = g_sums[g * HID + k] * inv;
#pragma unroll
    for (int j = 0; j < LABELS; j++) {
        float s = __ldg(&bc[j]);
#pragma unroll
        for (int k = 0; k < HID; k++) s = fmaf(p[k], __ldg(&Wc[k * LABELS + j]), s);
        out[g * LABELS + j] = s;
    }
}

// ---------------- launch -----------------------------------------------------
extern "C" void kernel_launch(void* const* d_in, const int* in_sizes, int n_in,
                              void* d_out, int out_size) {
    const int*   x    = (const int*)  d_in[0];
    const int*   ei   = (const int*)  d_in[1];
    const int*   batch= (const int*)  d_in[2];
    const float* emb  = (const float*)d_in[3];
    const float* W1   = (const float*)d_in[4];
    const float* b1   = (const float*)d_in[5];
    const float* W2   = (const float*)d_in[6];
    const float* b2   = (const float*)d_in[7];
    const float* Wc   = (const float*)d_in[8];
    const float* bc   = (const float*)d_in[9];
    float* out = (float*)d_out;

    int E = in_sizes[1] / 2;
    const int* src = ei;
    const int* dst = ei + E;

    int gn = (N_NODES + 255) / 256;
    int ge = (E + 255) / 256;
    int gw = (N_NODES * 32 + 255) / 256;     // warp per node

    k_init         <<<gn, 256>>>();
    k_deg          <<<ge, 256>>>(dst, E);
    k_scan1        <<<SCAN_NB, SCAN_BLK>>>();
    k_scan2_ew     <<<2, 128>>>(emb, W1);
    k_scan3_a1     <<<gn, 256>>>(x);
    k_scatter      <<<ge, 256>>>(src, dst, E);
    k_gather1_l2   <<<gw, 256>>>(b1, W2);
    k_gather2_pool <<<gw, 256>>>(b2, batch);
    k_final        <<<(N_GRAPHS + 255) / 256, 256>>>(Wc, bc, out);
}

// round 15
// speedup vs baseline: 1.1872x; 1.1872x over previous
#include <cuda_runtime.h>
#include <cuda_bf16.h>
#include <cuda_fp16.h>

#define N_NODES  100000
#define N_EDGES  3200000
#define N_GRAPHS 512
#define HID      16
#define LABELS   10
#define VOCAB    128

#define SCAN_BLK 1024
#define SCAN_NB  ((N_NODES + SCAN_BLK - 1) / SCAN_BLK)   // 98

// ---------------- scratch (device globals; zero-initialized at load) --------
// Invariant: g_deg, g_sums, g_cnt are zero on entry to every kernel_launch call
// (restored by k_pool / k_final at the end of the previous call).
__device__ int    g_deg   [N_NODES];
__device__ int    g_off   [N_NODES];
__device__ int    g_cursor[N_NODES];
__device__ int    g_bsum  [SCAN_NB];
__device__ int    g_bbase [SCAN_NB];
__device__ int    g_csr   [N_EDGES];
__device__ float  g_dinv  [N_NODES];
__device__ uint4  g_a1h   [N_NODES * 2];    // EW[x[i]] * dinv[i], fp16 (32B/row)
__device__ float4 g_h1    [N_NODES * 4];    // relu(layer1), f32
__device__ uint4  g_a2h   [N_NODES * 2];    // (h1 @ W2) * dinv[i], fp16 (32B/row)
__device__ float4 g_h2    [N_NODES * 4];    // relu(layer2), f32
__device__ float4 g_EW    [VOCAB * 4];      // emb @ W1 (f32)
__device__ float  g_sums  [N_GRAPHS * HID];
__device__ float  g_cnt   [N_GRAPHS];

__device__ __forceinline__ void red4(float4* p, float a, float b, float c, float d) {
    asm volatile("red.global.add.v4.f32 [%0], {%1,%2,%3,%4};"
                 :: "l"(p), "f"(a), "f"(b), "f"(c), "f"(d) : "memory");
}
__device__ __forceinline__ void redu(int* p) {
    asm volatile("red.global.add.u32 [%0], %1;" :: "l"(p), "r"(1u) : "memory");
}
__device__ __forceinline__ unsigned pack2(float a, float b) {
    __half2 h = __floats2half2_rn(a, b);
    return *reinterpret_cast<unsigned*>(&h);
}
__device__ __forceinline__ float2 unpack2(unsigned u) {
    __half2 h = *reinterpret_cast<__half2*>(&u);
    return __half22float2(h);
}

// ---------------- build ------------------------------------------------------

__global__ __launch_bounds__(256) void k_deg(const int* __restrict__ dst, int E) {
    int e = blockIdx.x * blockDim.x + threadIdx.x;
    if (e < E) redu(&g_deg[dst[e]]);
}

// shfl-based block scan (1024/block)
__global__ __launch_bounds__(SCAN_BLK) void k_scan1() {
    __shared__ int wtot[32];
    int gid = blockIdx.x * SCAN_BLK + threadIdx.x;
    int lane = threadIdx.x & 31, wid = threadIdx.x >> 5;
    int v = (gid < N_NODES) ? g_deg[gid] : 0;
    int x = v;
#pragma unroll
    for (int o = 1; o < 32; o <<= 1) {
        int t = __shfl_up_sync(0xffffffffu, x, o);
        if (lane >= o) x += t;
    }
    if (lane == 31) wtot[wid] = x;
    __syncthreads();
    if (threadIdx.x < 32) {
        int w = wtot[threadIdx.x];
        int y = w;
#pragma unroll
        for (int o = 1; o < 32; o <<= 1) {
            int t = __shfl_up_sync(0xffffffffu, y, o);
            if (threadIdx.x >= o) y += t;
        }
        wtot[threadIdx.x] = y - w;
        if (threadIdx.x == 31) g_bsum[blockIdx.x] = y;
    }
    __syncthreads();
    if (gid < N_NODES) g_off[gid] = x - v + wtot[wid];
}

// block 0: scan block totals; block 1: EW = emb @ W1
__global__ __launch_bounds__(128) void k_scan2_ew(const float* __restrict__ emb,
                                                  const float* __restrict__ W1) {
    int t = threadIdx.x;
    if (blockIdx.x == 0) {
        __shared__ int s[128];
        int v = (t < SCAN_NB) ? g_bsum[t] : 0;
        s[t] = v;
        __syncthreads();
#pragma unroll
        for (int off = 1; off < 128; off <<= 1) {
            int u = (t >= off) ? s[t - off] : 0;
            __syncthreads();
            s[t] += u;
            __syncthreads();
        }
        if (t < SCAN_NB) g_bbase[t] = s[t] - v;
    } else {
        __shared__ float sW[HID * HID];
        sW[t] = W1[t];
        sW[t + 128] = W1[t + 128];
        __syncthreads();
        float h[HID];
#pragma unroll
        for (int k = 0; k < HID; k++) h[k] = emb[t * HID + k];
#pragma unroll
        for (int q = 0; q < 4; q++) {
            float o[4];
#pragma unroll
            for (int jj = 0; jj < 4; jj++) {
                float s = 0.0f;
#pragma unroll
                for (int k = 0; k < HID; k++) s = fmaf(h[k], sW[k * HID + 4 * q + jj], s);
                o[jj] = s;
            }
            g_EW[t * 4 + q] = make_float4(o[0], o[1], o[2], o[3]);
        }
    }
}

// finalize offsets/cursors/dinv AND emit a1 = EW[x]*dinv as fp16 row
__global__ __launch_bounds__(256) void k_scan3_a1(const int* __restrict__ x) {
    int i = blockIdx.x * blockDim.x + threadIdx.x;
    if (i >= N_NODES) return;
    int o = g_off[i] + g_bbase[i >> 10];
    g_off[i] = o;
    g_cursor[i] = o;
    float di = rsqrtf((float)g_deg[i] + 1.0f);   // +1 self loop
    g_dinv[i] = di;
    const float4* r = &g_EW[x[i] * 4];
    float4 v0 = r[0], v1 = r[1], v2 = r[2], v3 = r[3];
    uint4 p0, p1;
    p0.x = pack2(v0.x * di, v0.y * di);  p0.y = pack2(v0.z * di, v0.w * di);
    p0.z = pack2(v1.x * di, v1.y * di);  p0.w = pack2(v1.z * di, v1.w * di);
    p1.x = pack2(v2.x * di, v2.y * di);  p1.y = pack2(v2.z * di, v2.w * di);
    p1.z = pack2(v3.x * di, v3.y * di);  p1.w = pack2(v3.z * di, v3.w * di);
    g_a1h[i * 2 + 0] = p0;
    g_a1h[i * 2 + 1] = p1;
}

__global__ __launch_bounds__(256) void k_scatter(const int* __restrict__ src,
                                                 const int* __restrict__ dst, int E) {
    int e = blockIdx.x * blockDim.x + threadIdx.x;
    if (e >= E) return;
    int pos = atomicAdd(&g_cursor[dst[e]], 1);
    g_csr[pos] = src[e];
}

// ---------------- fp16 gather core (warp/node, 2 lanes per edge) ------------
// After the reduction, lane 0 holds features 0-7 in a[0..7], lane 1 features 8-15.
__device__ __forceinline__ void gather_fp16(const uint4* __restrict__ val,
                                            int node, int lane, float* a) {
    int eq = lane >> 1, fj = lane & 1;
    int off = __ldg(&g_off[node]);
    int deg = __ldg(&g_deg[node]);
    for (int base = 0; base < deg; base += 16) {
        int e = base + eq;
        if (e < deg) {
            int s = __ldg(&g_csr[off + e]);
            uint4 v = __ldg(&val[s * 2 + fj]);    // 2 lanes -> one 32B sector
            float2 f;
            f = unpack2(v.x); a[0] += f.x; a[1] += f.y;
            f = unpack2(v.y); a[2] += f.x; a[3] += f.y;
            f = unpack2(v.z); a[4] += f.x; a[5] += f.y;
            f = unpack2(v.w); a[6] += f.x; a[7] += f.y;
        }
    }
#pragma unroll
    for (int o = 16; o >= 2; o >>= 1) {
#pragma unroll
        for (int k = 0; k < 8; k++)
            a[k] += __shfl_down_sync(0xffffffffu, a[k], o);
    }
}

// layer-1 gather -> g_h1 (f32)
__global__ __launch_bounds__(256) void k_gather1(const float* __restrict__ b1) {
    int n = (blockIdx.x * blockDim.x + threadIdx.x) >> 5;
    if (n >= N_NODES) return;
    int lane = threadIdx.x & 31;
    float a[8] = {0.f,0.f,0.f,0.f,0.f,0.f,0.f,0.f};
    gather_fp16(g_a1h, n, lane, a);
    if (lane < 2) {
        float di = __ldg(&g_dinv[n]);
        uint4 sv = __ldg(&g_a1h[n * 2 + lane]);
        float2 f;
        f = unpack2(sv.x); a[0] += f.x; a[1] += f.y;
        f = unpack2(sv.y); a[2] += f.x; a[3] += f.y;
        f = unpack2(sv.z); a[4] += f.x; a[5] += f.y;
        f = unpack2(sv.w); a[6] += f.x; a[7] += f.y;
        float4 bA = __ldg((const float4*)b1 + 2 * lane);
        float4 bB = __ldg((const float4*)b1 + 2 * lane + 1);
        float4 o0, o1;
        o0.x = fmaxf(a[0] * di + bA.x, 0.0f);
        o0.y = fmaxf(a[1] * di + bA.y, 0.0f);
        o0.z = fmaxf(a[2] * di + bA.z, 0.0f);
        o0.w = fmaxf(a[3] * di + bA.w, 0.0f);
        o1.x = fmaxf(a[4] * di + bB.x, 0.0f);
        o1.y = fmaxf(a[5] * di + bB.y, 0.0f);
        o1.z = fmaxf(a[6] * di + bB.z, 0.0f);
        o1.w = fmaxf(a[7] * di + bB.w, 0.0f);
        g_h1[n * 4 + 2 * lane + 0] = o0;
        g_h1[n * 4 + 2 * lane + 1] = o1;
    }
}

// a2[i] = (h1[i] @ W2) * dinv[i] -> fp16 row
__global__ __launch_bounds__(256) void k_l2(const float* __restrict__ W2) {
    __shared__ float sW[HID * HID];
    if (threadIdx.x < HID * HID) sW[threadIdx.x] = W2[threadIdx.x];
    __syncthreads();
    int i = blockIdx.x * blockDim.x + threadIdx.x;
    if (i >= N_NODES) return;
    float h[HID];
#pragma unroll
    for (int q = 0; q < 4; q++) {
        float4 v = g_h1[i * 4 + q];
        h[4 * q + 0] = v.x; h[4 * q + 1] = v.y; h[4 * q + 2] = v.z; h[4 * q + 3] = v.w;
    }
    float o[HID];
#pragma unroll
    for (int j = 0; j < HID; j++) o[j] = 0.0f;
#pragma unroll
    for (int k = 0; k < HID; k++)
#pragma unroll
        for (int j = 0; j < HID; j++) o[j] = fmaf(h[k], sW[k * HID + j], o[j]);
    float di = g_dinv[i];
    uint4 p0, p1;
    p0.x = pack2(o[0]*di,  o[1]*di);   p0.y = pack2(o[2]*di,  o[3]*di);
    p0.z = pack2(o[4]*di,  o[5]*di);   p0.w = pack2(o[6]*di,  o[7]*di);
    p1.x = pack2(o[8]*di,  o[9]*di);   p1.y = pack2(o[10]*di, o[11]*di);
    p1.z = pack2(o[12]*di, o[13]*di);  p1.w = pack2(o[14]*di, o[15]*di);
    g_a2h[i * 2 + 0] = p0;
    g_a2h[i * 2 + 1] = p1;
}

// layer-2 gather -> g_h2 (f32)
__global__ __launch_bounds__(256) void k_gather2(const float* __restrict__ b2) {
    int n = (blockIdx.x * blockDim.x + threadIdx.x) >> 5;
    if (n >= N_NODES) return;
    int lane = threadIdx.x & 31;
    float a[8] = {0.f,0.f,0.f,0.f,0.f,0.f,0.f,0.f};
    gather_fp16(g_a2h, n, lane, a);
    if (lane < 2) {
        float di = __ldg(&g_dinv[n]);
        uint4 sv = __ldg(&g_a2h[n * 2 + lane]);
        float2 f;
        f = unpack2(sv.x); a[0] += f.x; a[1] += f.y;
        f = unpack2(sv.y); a[2] += f.x; a[3] += f.y;
        f = unpack2(sv.z); a[4] += f.x; a[5] += f.y;
        f = unpack2(sv.w); a[6] += f.x; a[7] += f.y;
        float4 bA = __ldg((const float4*)b2 + 2 * lane);
        float4 bB = __ldg((const float4*)b2 + 2 * lane + 1);
        float4 o0, o1;
        o0.x = fmaxf(a[0] * di + bA.x, 0.0f);
        o0.y = fmaxf(a[1] * di + bA.y, 0.0f);
        o0.z = fmaxf(a[2] * di + bA.z, 0.0f);
        o0.w = fmaxf(a[3] * di + bA.w, 0.0f);
        o1.x = fmaxf(a[4] * di + bB.x, 0.0f);
        o1.y = fmaxf(a[5] * di + bB.y, 0.0f);
        o1.z = fmaxf(a[6] * di + bB.z, 0.0f);
        o1.w = fmaxf(a[7] * di + bB.w, 0.0f);
        g_h2[n * 4 + 2 * lane + 0] = o0;
        g_h2[n * 4 + 2 * lane + 1] = o1;
    }
}

// pooling (R3-proven) + re-zero g_deg for the next call
__global__ __launch_bounds__(256) void k_pool(const int* __restrict__ batch) {
    int i = blockIdx.x * blockDim.x + threadIdx.x;
    int lane = threadIdx.x & 31;
    float h[HID];
    int b = -1;
    if (i < N_NODES) {
        b = batch[i];
#pragma unroll
        for (int q = 0; q < 4; q++) {
            float4 v = g_h2[i * 4 + q];
            h[4*q+0] = v.x; h[4*q+1] = v.y; h[4*q+2] = v.z; h[4*q+3] = v.w;
        }
        g_deg[i] = 0;                    // restore invariant for next launch
    } else {
#pragma unroll
        for (int k = 0; k < HID; k++) h[k] = 0.0f;
    }
    int b0 = __shfl_sync(0xffffffffu, b, 0);
    bool uniform = __all_sync(0xffffffffu, b == b0);
    if (uniform && b0 >= 0) {
#pragma unroll
        for (int k = 0; k < HID; k++) {
#pragma unroll
            for (int off = 16; off > 0; off >>= 1)
                h[k] += __shfl_down_sync(0xffffffffu, h[k], off);
        }
        if (lane == 0) {
            float4* p = (float4*)&g_sums[b0 * HID];
#pragma unroll
            for (int q = 0; q < 4; q++)
                red4(p + q, h[4*q], h[4*q+1], h[4*q+2], h[4*q+3]);
            atomicAdd(&g_cnt[b0], 32.0f);
        }
    } else if (b >= 0) {
        float4* p = (float4*)&g_sums[b * HID];
#pragma unroll
        for (int q = 0; q < 4; q++)
            red4(p + q, h[4*q], h[4*q+1], h[4*q+2], h[4*q+3]);
        atomicAdd(&g_cnt[b], 1.0f);
    }
}

// out = pooled @ Wc + bc; then re-zero sums/cnt for the next call
__global__ __launch_bounds__(256) void k_final(const float* __restrict__ Wc,
                                               const float* __restrict__ bc,
                                               float* __restrict__ out) {
    int g = blockIdx.x * blockDim.x + threadIdx.x;
    if (g >= N_GRAPHS) return;
    float inv = 1.0f / fmaxf(g_cnt[g], 1.0f);
    float p[HID];
#pragma unroll
    for (int k = 0; k < HID; k++) p[k] = g_sums[g * HID + k] * inv;
#pragma unroll
    for (int j = 0; j < LABELS; j++) {
        float s = __ldg(&bc[j]);
#pragma unroll
        for (int k = 0; k < HID; k++) s = fmaf(p[k], __ldg(&Wc[k * LABELS + j]), s);
        out[g * LABELS + j] = s;
    }
    g_cnt[g] = 0.0f;                     // restore invariant
#pragma unroll
    for (int k = 0; k < HID; k++) g_sums[g * HID + k] = 0.0f;
}

// ---------------- launch -----------------------------------------------------
extern "C" void kernel_launch(void* const* d_in, const int* in_sizes, int n_in,
                              void* d_out, int out_size) {
    const int*   x    = (const int*)  d_in[0];
    const int*   ei   = (const int*)  d_in[1];
    const int*   batch= (const int*)  d_in[2];
    const float* emb  = (const float*)d_in[3];
    const float* W1   = (const float*)d_in[4];
    const float* b1   = (const float*)d_in[5];
    const float* W2   = (const float*)d_in[6];
    const float* b2   = (const float*)d_in[7];
    const float* Wc   = (const float*)d_in[8];
    const float* bc   = (const float*)d_in[9];
    float* out = (float*)d_out;

    int E = in_sizes[1] / 2;
    const int* src = ei;
    const int* dst = ei + E;

    int gn = (N_NODES + 255) / 256;
    int ge = (E + 255) / 256;
    int gw = (N_NODES * 32 + 255) / 256;     // warp per node

    k_deg      <<<ge, 256>>>(dst, E);
    k_scan1    <<<SCAN_NB, SCAN_BLK>>>();
    k_scan2_ew <<<2, 128>>>(emb, W1);
    k_scan3_a1 <<<gn, 256>>>(x);
    k_scatter  <<<ge, 256>>>(src, dst, E);
    k_gather1  <<<gw, 256>>>(b1);
    k_l2       <<<gn, 256>>>(W2);
    k_gather2  <<<gw, 256>>>(b2);
    k_pool     <<<gn, 256>>>(batch);
    k_final    <<<(N_GRAPHS + 255) / 256, 256>>>(Wc, bc, out);
}

// round 16
// speedup vs baseline: 1.2393x; 1.0439x over previous
#include <cuda_runtime.h>
#include <cuda_bf16.h>

#define N_NODES  100000
#define N_EDGES  3200000
#define N_GRAPHS 512
#define HID      16
#define LABELS   10
#define VOCAB    128

#define SCAN_BLK 1024
#define SCAN_NB  ((N_NODES + SCAN_BLK - 1) / SCAN_BLK)   // 98

// ---------------- scratch (device globals; zero-initialized at load) --------
// Invariant: g_deg, g_sums, g_cnt are zero on entry to every kernel_launch call
// (zeros restored by k_pool / k_final at the end of each call).
__device__ int    g_deg   [N_NODES];
__device__ int    g_off   [N_NODES];
__device__ int    g_cursor[N_NODES];
__device__ int    g_bsum  [SCAN_NB];
__device__ int    g_bbase [SCAN_NB];
__device__ int    g_csr   [N_EDGES];
__device__ float  g_dinv  [N_NODES];
__device__ float4 g_a1    [N_NODES * 4];    // EW[x[i]] * dinv[i]
__device__ float4 g_h1    [N_NODES * 4];    // relu(layer1)
__device__ float4 g_a2    [N_NODES * 4];    // (h1 @ W2) * dinv[i]
__device__ float4 g_h2    [N_NODES * 4];    // relu(layer2)
__device__ float4 g_EW    [VOCAB * 4];      // emb @ W1
__device__ float  g_sums  [N_GRAPHS * HID];
__device__ float  g_cnt   [N_GRAPHS];

__device__ __forceinline__ void red4(float4* p, float a, float b, float c, float d) {
    asm volatile("red.global.add.v4.f32 [%0], {%1,%2,%3,%4};"
                 :: "l"(p), "f"(a), "f"(b), "f"(c), "f"(d) : "memory");
}
__device__ __forceinline__ void redu(int* p) {
    asm volatile("red.global.add.u32 [%0], %1;" :: "l"(p), "r"(1u) : "memory");
}

// ---------------- build ------------------------------------------------------

__global__ __launch_bounds__(256) void k_deg(const int* __restrict__ dst, int E) {
    int e = blockIdx.x * blockDim.x + threadIdx.x;
    if (e < E) redu(&g_deg[dst[e]]);     // dst reused by scatter: default policy
}

// shfl-based block scan (1024/block)
__global__ __launch_bounds__(SCAN_BLK) void k_scan1() {
    __shared__ int wtot[32];
    int gid = blockIdx.x * SCAN_BLK + threadIdx.x;
    int lane = threadIdx.x & 31, wid = threadIdx.x >> 5;
    int v = (gid < N_NODES) ? g_deg[gid] : 0;
    int x = v;
#pragma unroll
    for (int o = 1; o < 32; o <<= 1) {
        int t = __shfl_up_sync(0xffffffffu, x, o);
        if (lane >= o) x += t;
    }
    if (lane == 31) wtot[wid] = x;
    __syncthreads();
    if (threadIdx.x < 32) {
        int w = wtot[threadIdx.x];
        int y = w;
#pragma unroll
        for (int o = 1; o < 32; o <<= 1) {
            int t = __shfl_up_sync(0xffffffffu, y, o);
            if (threadIdx.x >= o) y += t;
        }
        wtot[threadIdx.x] = y - w;
        if (threadIdx.x == 31) g_bsum[blockIdx.x] = y;
    }
    __syncthreads();
    if (gid < N_NODES) g_off[gid] = x - v + wtot[wid];
}

// block 0: scan block totals; block 1: EW = emb @ W1
__global__ __launch_bounds__(128) void k_scan2_ew(const float* __restrict__ emb,
                                                  const float* __restrict__ W1) {
    int t = threadIdx.x;
    if (blockIdx.x == 0) {
        __shared__ int s[128];
        int v = (t < SCAN_NB) ? g_bsum[t] : 0;
        s[t] = v;
        __syncthreads();
#pragma unroll
        for (int off = 1; off < 128; off <<= 1) {
            int u = (t >= off) ? s[t - off] : 0;
            __syncthreads();
            s[t] += u;
            __syncthreads();
        }
        if (t < SCAN_NB) g_bbase[t] = s[t] - v;
    } else {
        __shared__ float sW[HID * HID];
        sW[t] = W1[t];
        sW[t + 128] = W1[t + 128];
        __syncthreads();
        float h[HID];
#pragma unroll
        for (int k = 0; k < HID; k++) h[k] = emb[t * HID + k];
#pragma unroll
        for (int q = 0; q < 4; q++) {
            float o[4];
#pragma unroll
            for (int jj = 0; jj < 4; jj++) {
                float s = 0.0f;
#pragma unroll
                for (int k = 0; k < HID; k++) s = fmaf(h[k], sW[k * HID + 4 * q + jj], s);
                o[jj] = s;
            }
            g_EW[t * 4 + q] = make_float4(o[0], o[1], o[2], o[3]);
        }
    }
}

// finalize offsets/cursors/dinv AND emit a1 = EW[x]*dinv
__global__ __launch_bounds__(256) void k_scan3_a1(const int* __restrict__ x) {
    int i = blockIdx.x * blockDim.x + threadIdx.x;
    if (i >= N_NODES) return;
    int o = g_off[i] + g_bbase[i >> 10];
    g_off[i] = o;
    g_cursor[i] = o;
    float di = rsqrtf((float)g_deg[i] + 1.0f);   // +1 self loop
    g_dinv[i] = di;
    const float4* r = &g_EW[__ldcs(&x[i]) * 4];  // x read once per call
#pragma unroll
    for (int q = 0; q < 4; q++) {
        float4 v = r[q];
        g_a1[i * 4 + q] = make_float4(v.x * di, v.y * di, v.z * di, v.w * di);
    }
}

__global__ __launch_bounds__(256) void k_scatter(const int* __restrict__ src,
                                                 const int* __restrict__ dst, int E) {
    int e = blockIdx.x * blockDim.x + threadIdx.x;
    if (e >= E) return;
    int pos = atomicAdd(&g_cursor[dst[e]], 1);
    g_csr[pos] = __ldcs(&src[e]);        // src read once per call
}

// ---------------- gather core (warp/node, 4 lanes per edge) -----------------

// layer-1 gather -> g_h1 (csr first read: keep resident for gather2)
__global__ __launch_bounds__(256) void k_gather1(const float* __restrict__ b1) {
    int n = (blockIdx.x * blockDim.x + threadIdx.x) >> 5;
    if (n >= N_NODES) return;
    int lane = threadIdx.x & 31;
    int eq = lane >> 2, fj = lane & 3;
    int off = __ldg(&g_off[n]);
    int deg = __ldg(&g_deg[n]);

    float4 acc = make_float4(0.f, 0.f, 0.f, 0.f);
    for (int base = 0; base < deg; base += 8) {
        int e = base + eq;
        if (e < deg) {
            int s = __ldg(&g_csr[off + e]);
            float4 v = __ldg(&g_a1[s * 4 + fj]);
            acc.x += v.x; acc.y += v.y; acc.z += v.z; acc.w += v.w;
        }
    }
#pragma unroll
    for (int o = 16; o >= 4; o >>= 1) {
        acc.x += __shfl_down_sync(0xffffffffu, acc.x, o);
        acc.y += __shfl_down_sync(0xffffffffu, acc.y, o);
        acc.z += __shfl_down_sync(0xffffffffu, acc.z, o);
        acc.w += __shfl_down_sync(0xffffffffu, acc.w, o);
    }
    if (lane < 4) {
        float di = __ldg(&g_dinv[n]);
        float4 self = __ldg(&g_a1[n * 4 + lane]);
        float4 b = __ldg((const float4*)b1 + lane);
        float4 h;
        h.x = fmaxf((acc.x + self.x) * di + b.x, 0.0f);
        h.y = fmaxf((acc.y + self.y) * di + b.y, 0.0f);
        h.z = fmaxf((acc.z + self.z) * di + b.z, 0.0f);
        h.w = fmaxf((acc.w + self.w) * di + b.w, 0.0f);
        g_h1[n * 4 + lane] = h;
    }
}

// a2[i] = (h1[i] @ W2) * dinv[i]
__global__ __launch_bounds__(256) void k_l2(const float* __restrict__ W2) {
    __shared__ float sW[HID * HID];
    if (threadIdx.x < HID * HID) sW[threadIdx.x] = W2[threadIdx.x];
    __syncthreads();
    int i = blockIdx.x * blockDim.x + threadIdx.x;
    if (i >= N_NODES) return;
    float h[HID];
#pragma unroll
    for (int q = 0; q < 4; q++) {
        float4 v = __ldcs(&g_h1[i * 4 + q]);     // h1 read once
        h[4 * q + 0] = v.x; h[4 * q + 1] = v.y; h[4 * q + 2] = v.z; h[4 * q + 3] = v.w;
    }
    float o[HID];
#pragma unroll
    for (int j = 0; j < HID; j++) o[j] = 0.0f;
#pragma unroll
    for (int k = 0; k < HID; k++)
#pragma unroll
        for (int j = 0; j < HID; j++) o[j] = fmaf(h[k], sW[k * HID + j], o[j]);
    float di = g_dinv[i];
#pragma unroll
    for (int q = 0; q < 4; q++)
        g_a2[i * 4 + q] = make_float4(o[4*q]*di, o[4*q+1]*di, o[4*q+2]*di, o[4*q+3]*di);
}

// layer-2 gather -> g_h2 (csr last read: stream it out of L2)
__global__ __launch_bounds__(256) void k_gather2(const float* __restrict__ b2) {
    int n = (blockIdx.x * blockDim.x + threadIdx.x) >> 5;
    if (n >= N_NODES) return;
    int lane = threadIdx.x & 31;
    int eq = lane >> 2, fj = lane & 3;
    int off = __ldg(&g_off[n]);
    int deg = __ldg(&g_deg[n]);

    float4 acc = make_float4(0.f, 0.f, 0.f, 0.f);
    for (int base = 0; base < deg; base += 8) {
        int e = base + eq;
        if (e < deg) {
            int s = __ldcs(&g_csr[off + e]);
            float4 v = __ldg(&g_a2[s * 4 + fj]);
            acc.x += v.x; acc.y += v.y; acc.z += v.z; acc.w += v.w;
        }
    }
#pragma unroll
    for (int o = 16; o >= 4; o >>= 1) {
        acc.x += __shfl_down_sync(0xffffffffu, acc.x, o);
        acc.y += __shfl_down_sync(0xffffffffu, acc.y, o);
        acc.z += __shfl_down_sync(0xffffffffu, acc.z, o);
        acc.w += __shfl_down_sync(0xffffffffu, acc.w, o);
    }
    if (lane < 4) {
        float di = __ldg(&g_dinv[n]);
        float4 self = __ldg(&g_a2[n * 4 + lane]);
        float4 b = __ldg((const float4*)b2 + lane);
        float4 o;
        o.x = fmaxf((acc.x + self.x) * di + b.x, 0.0f);
        o.y = fmaxf((acc.y + self.y) * di + b.y, 0.0f);
        o.z = fmaxf((acc.z + self.z) * di + b.z, 0.0f);
        o.w = fmaxf((acc.w + self.w) * di + b.w, 0.0f);
        g_h2[n * 4 + lane] = o;
    }
}

// pooling (R3-proven) + restore g_deg=0 for the next call
__global__ __launch_bounds__(256) void k_pool(const int* __restrict__ batch) {
    int i = blockIdx.x * blockDim.x + threadIdx.x;
    int lane = threadIdx.x & 31;
    float h[HID];
    int b = -1;
    if (i < N_NODES) {
        b = __ldcs(&batch[i]);
#pragma unroll
        for (int q = 0; q < 4; q++) {
            float4 v = __ldcs(&g_h2[i * 4 + q]);   // h2 read once
            h[4*q+0] = v.x; h[4*q+1] = v.y; h[4*q+2] = v.z; h[4*q+3] = v.w;
        }
        g_deg[i] = 0;                    // restore invariant (deg last used in gather2)
    } else {
#pragma unroll
        for (int k = 0; k < HID; k++) h[k] = 0.0f;
    }
    int b0 = __shfl_sync(0xffffffffu, b, 0);
    bool uniform = __all_sync(0xffffffffu, b == b0);
    if (uniform && b0 >= 0) {
#pragma unroll
        for (int k = 0; k < HID; k++) {
#pragma unroll
            for (int off = 16; off > 0; off >>= 1)
                h[k] += __shfl_down_sync(0xffffffffu, h[k], off);
        }
        if (lane == 0) {
            float4* p = (float4*)&g_sums[b0 * HID];
#pragma unroll
            for (int q = 0; q < 4; q++)
                red4(p + q, h[4*q], h[4*q+1], h[4*q+2], h[4*q+3]);
            atomicAdd(&g_cnt[b0], 32.0f);
        }
    } else if (b >= 0) {
        float4* p = (float4*)&g_sums[b * HID];
#pragma unroll
        for (int q = 0; q < 4; q++)
            red4(p + q, h[4*q], h[4*q+1], h[4*q+2], h[4*q+3]);
        atomicAdd(&g_cnt[b], 1.0f);
    }
}

// out = pooled @ Wc + bc; restore sums/cnt zeros for the next call
__global__ __launch_bounds__(256) void k_final(const float* __restrict__ Wc,
                                               const float* __restrict__ bc,
                                               float* __restrict__ out) {
    int g = blockIdx.x * blockDim.x + threadIdx.x;
    if (g >= N_GRAPHS) return;
    float inv = 1.0f / fmaxf(g_cnt[g], 1.0f);
    float p[HID];
#pragma unroll
    for (int k = 0; k < HID; k++) p[k] = g_sums[g * HID + k] * inv;
#pragma unroll
    for (int j = 0; j < LABELS; j++) {
        float s = __ldg(&bc[j]);
#pragma unroll
        for (int k = 0; k < HID; k++) s = fmaf(p[k], __ldg(&Wc[k * LABELS + j]), s);
        out[g * LABELS + j] = s;
    }
    g_cnt[g] = 0.0f;                     // restore invariant
#pragma unroll
    for (int k = 0; k < HID; k++) g_sums[g * HID + k] = 0.0f;
}

// ---------------- launch -----------------------------------------------------
extern "C" void kernel_launch(void* const* d_in, const int* in_sizes, int n_in,
                              void* d_out, int out_size) {
    const int*   x    = (const int*)  d_in[0];
    const int*   ei   = (const int*)  d_in[1];
    const int*   batch= (const int*)  d_in[2];
    const float* emb  = (const float*)d_in[3];
    const float* W1   = (const float*)d_in[4];
    const float* b1   = (const float*)d_in[5];
    const float* W2   = (const float*)d_in[6];
    const float* b2   = (const float*)d_in[7];
    const float* Wc   = (const float*)d_in[8];
    const float* bc   = (const float*)d_in[9];
    float* out = (float*)d_out;

    int E = in_sizes[1] / 2;
    const int* src = ei;
    const int* dst = ei + E;

    int gn = (N_NODES + 255) / 256;
    int ge = (E + 255) / 256;
    int gw = (N_NODES * 32 + 255) / 256;     // warp per node

    k_deg      <<<ge, 256>>>(dst, E);
    k_scan1    <<<SCAN_NB, SCAN_BLK>>>();
    k_scan2_ew <<<2, 128>>>(emb, W1);
    k_scan3_a1 <<<gn, 256>>>(x);
    k_scatter  <<<ge, 256>>>(src, dst, E);
    k_gather1  <<<gw, 256>>>(b1);
    k_l2       <<<gn, 256>>>(W2);
    k_gather2  <<<gw, 256>>>(b2);
    k_pool     <<<gn, 256>>>(batch);
    k_final    <<<(N_GRAPHS + 255) / 256, 256>>>(Wc, bc, out);
}